// round 12
// baseline (speedup 1.0000x reference)
#include <cuda_runtime.h>

// ---------------------------------------------------------------------------
// encoderOnlyComplex: VoxelMorph-style registration network, fp32.
// Round 12: R11 winner + (a) inorm_fin folded into norm_prelu (stats from
// partials computed in-block), (b) flow composition fused into the final
// vecint squaring step. Conv core untouched.
// ---------------------------------------------------------------------------

#define V64 262144            // 64^3
#define PYR_TOT 299584

__device__ float g_bufA[2 * 32 * V64];
__device__ float g_bufB[2 * 32 * V64];
__device__ float g_xs[16 * PYR_TOT];
__device__ float g_ys[16 * PYR_TOT];
__device__ float g_cat[32 * V64];
__device__ float g_feat1[32 * V64];
__device__ float g_feat2[27 * V64];
__device__ float g_vecA[3 * V64];
__device__ float g_up[3 * V64];
__device__ float g_part[64 * 16];     // per-(nc) partials: [nc][0..7]=s, [nc][8..15]=s2
__device__ float g_wrepAll[202716];

// ---- cp.async helpers ----
__device__ __forceinline__ void cp_async4(void* smem, const void* gmem, bool pred) {
    unsigned s = (unsigned)__cvta_generic_to_shared(smem);
    int sz = pred ? 4 : 0;
    asm volatile("cp.async.ca.shared.global [%0], [%1], 4, %2;"
                 :: "r"(s), "l"(gmem), "r"(sz));
}
#define CP_COMMIT() asm volatile("cp.async.commit_group;")
#define CP_WAIT1()  asm volatile("cp.async.wait_group 1;")
#define CP_WAIT0()  asm volatile("cp.async.wait_group 0;")

__global__ void repack_all(const float* __restrict__ e1, const float* __restrict__ e2,
                           const float* __restrict__ e3, const float* __restrict__ w1,
                           const float* __restrict__ w2, const float* __restrict__ w3,
                           float* __restrict__ wr) {
    const int CIN[12]  = {1,16,32, 32,32,27, 32,32,27, 32,32,27};
    const int COUT[12] = {16,32,16, 32,27,3, 32,27,3, 32,27,3};
    const int COP[12]  = {16,32,16, 32,32,4, 32,32,4, 32,32,4};
    const int OFF[12]  = {0,432,14256, 28080,55728,83376,
                          86292,113940,141588, 144504,172152,199800};
    int id = blockIdx.y;
    int cin = CIN[id], cout = COUT[id], cop = COP[id];
    int tot = cin * 27 * cop;
    int i = blockIdx.x * blockDim.x + threadIdx.x;
    if (i >= tot) return;
    const float* src;
    if (id == 0) src = e1;
    else if (id == 1) src = e2;
    else if (id == 2) src = e3;
    else {
        int l = (id - 3) / 3, j = (id - 3) % 3;
        const float* base = (j == 0) ? w1 : (j == 1) ? w2 : w3;
        src = base + (size_t)l * cout * cin * 27;
    }
    int co = i % cop;
    int k  = (i / cop) % 27;
    int ci = i / (cop * 27);
    wr[OFF[id] + i] = (co < cout) ? src[((size_t)co * cin + ci) * 27 + k] : 0.f;
}

// ---------------------------------------------------------------------------
// Conv v6 (measured best): 128 thr, JCO co-groups via blockIdx.y, tile
// 32x4x4, double-buffered cp.async staging. UNCHANGED.
// ---------------------------------------------------------------------------
template <int JCO>
__global__ __launch_bounds__(128)
void conv_tiled6(const float* __restrict__ in, const float* __restrict__ wr,
                 const float* __restrict__ bias, float* __restrict__ out,
                 int Cin, int Cout, int COP, int D, int relu,
                 int tilesX, int tilesY) {
    const int W = 4 * JCO;
    __shared__ __align__(16) float s_in[2][6 * 6 * 36];
    __shared__ __align__(16) float s_w[2][27 * 16];

    const int tid = threadIdx.x;
    const int tx = tid & 7;
    const int ty = (tid >> 3) & 3;
    const int tg = tid >> 5;

    int bx = blockIdx.x;
    const int tX = bx % tilesX;
    bx /= tilesX;
    const int tY = bx % tilesY;
    const int tZ = bx / tilesY;
    const int n  = blockIdx.z;

    const int X0 = tX * 32;
    const int Y0 = tY * 4;
    const int Z0 = tZ * 4;
    const int coB = blockIdx.y * W;
    const int x0 = X0 + (tx << 2);
    const int yo = Y0 + ty;
    const int vox = D * D * D;

    float acc[4 * JCO * 4];
    #pragma unroll
    for (int j = 0; j < JCO; j++) {
        int co = coB + tg * JCO + j;
        float b = (co < Cout) ? bias[co] : 0.f;
        #pragma unroll
        for (int zo = 0; zo < 4; zo++)
            #pragma unroll
            for (int xo = 0; xo < 4; xo++) acc[(zo * JCO + j) * 4 + xo] = b;
    }

    const float* inN = in + (size_t)n * Cin * vox;

    auto stage = [&](int ci, int buf) {
        for (int i = tid; i < 27 * W; i += 128)
            cp_async4(&s_w[buf][(i / W) * W + (i % W)],
                      &wr[((size_t)ci * 27 + i / W) * COP + coB + (i % W)], true);
        const float* inC = inN + (size_t)ci * vox;
        for (int i = tid; i < 1224; i += 128) {
            int p = i / 204;
            int r = (i % 204) / 34;
            int c = i % 34;
            int zz = Z0 - 1 + p;
            int yy = Y0 - 1 + r;
            int xx = X0 - 1 + c;
            bool ok = (unsigned)zz < (unsigned)D && (unsigned)yy < (unsigned)D &&
                      (unsigned)xx < (unsigned)D;
            int zc = min(max(zz, 0), D - 1);
            int yc = min(max(yy, 0), D - 1);
            int xc = min(max(xx, 0), D - 1);
            cp_async4(&s_in[buf][(p * 6 + r) * 36 + c],
                      &inC[((size_t)zc * D + yc) * D + xc], ok);
        }
        CP_COMMIT();
    };

    stage(0, 0);
    for (int ci = 0; ci < Cin; ci++) {
        if (ci + 1 < Cin) {
            stage(ci + 1, (ci + 1) & 1);
            CP_WAIT1();
        } else {
            CP_WAIT0();
        }
        __syncthreads();

        const int buf = ci & 1;
        #pragma unroll
        for (int kz = 0; kz < 3; kz++) {
            #pragma unroll
            for (int ky = 0; ky < 3; ky++) {
                const int k0 = kz * 9 + ky * 3;
                float wk[3][JCO];
                if (JCO == 4) {
                    #pragma unroll
                    for (int kx = 0; kx < 3; kx++) {
                        float4 w4 = *(const float4*)&s_w[buf][(k0 + kx) * 16 + tg * 4];
                        wk[kx][0] = w4.x; wk[kx][1] = w4.y;
                        wk[kx][2] = w4.z; wk[kx][3] = w4.w;
                    }
                } else {
                    #pragma unroll
                    for (int kx = 0; kx < 3; kx++)
                        wk[kx][0] = s_w[buf][(k0 + kx) * W + tg];
                }
                #pragma unroll
                for (int zo = 0; zo < 4; zo++) {
                    const float* bp =
                        &s_in[buf][((kz + zo) * 6 + ty + ky) * 36 + (tx << 2)];
                    float4 a = *(const float4*)bp;
                    float4 b = *(const float4*)(bp + 4);
                    float v[6] = {a.x, a.y, a.z, a.w, b.x, b.y};
                    #pragma unroll
                    for (int kx = 0; kx < 3; kx++)
                        #pragma unroll
                        for (int j = 0; j < JCO; j++)
                            #pragma unroll
                            for (int xo = 0; xo < 4; xo++)
                                acc[(zo * JCO + j) * 4 + xo] +=
                                    v[kx + xo] * wk[kx][j];
                }
            }
        }
        __syncthreads();
    }

    if (x0 < D) {
        #pragma unroll
        for (int zo = 0; zo < 4; zo++) {
            int z = Z0 + zo;
            #pragma unroll
            for (int j = 0; j < JCO; j++) {
                int co = coB + tg * JCO + j;
                if (co < Cout) {
                    float4 r;
                    float* a = &acc[(zo * JCO + j) * 4];
                    r.x = a[0]; r.y = a[1]; r.z = a[2]; r.w = a[3];
                    if (relu) {
                        r.x = fmaxf(r.x, 0.f); r.y = fmaxf(r.y, 0.f);
                        r.z = fmaxf(r.z, 0.f); r.w = fmaxf(r.w, 0.f);
                    }
                    *(float4*)(out + ((size_t)n * Cout + co) * vox +
                               ((size_t)z * D + yo) * D + x0) = r;
                }
            }
        }
    }
}

// Fallback direct conv for tiny volumes (D < 16).
__global__ void conv3x3x3(const float* __restrict__ in, const float* __restrict__ w,
                          const float* __restrict__ bias, float* __restrict__ out,
                          int Cin, int D, int do_relu) {
    const int vox = D * D * D;
    const int co = blockIdx.y;
    const int n  = blockIdx.z;
    extern __shared__ float ws[];
    const int nw = Cin * 27;
    for (int i = threadIdx.x; i < nw; i += blockDim.x)
        ws[i] = w[(size_t)co * nw + i];
    __syncthreads();

    int idx = blockIdx.x * blockDim.x + threadIdx.x;
    if (idx >= vox) return;
    int x = idx % D;
    int t = idx / D;
    int y = t % D;
    int z = t / D;

    const float* inb = in + (size_t)n * Cin * vox;
    float acc = bias[co];
    for (int ci = 0; ci < Cin; ci++) {
        const float* ip = inb + (size_t)ci * vox;
        const float* wp = ws + ci * 27;
        #pragma unroll
        for (int kz = 0; kz < 3; kz++) {
            int zz = z + kz - 1;
            if ((unsigned)zz >= (unsigned)D) continue;
            #pragma unroll
            for (int ky = 0; ky < 3; ky++) {
                int yy = y + ky - 1;
                if ((unsigned)yy >= (unsigned)D) continue;
                const float* row = ip + ((size_t)zz * D + yy) * D;
                #pragma unroll
                for (int kx = 0; kx < 3; kx++) {
                    int xx = x + kx - 1;
                    if ((unsigned)xx >= (unsigned)D) continue;
                    acc += row[xx] * wp[kz * 9 + ky * 3 + kx];
                }
            }
        }
    }
    if (do_relu) acc = fmaxf(acc, 0.f);
    out[((size_t)n * gridDim.y + co) * vox + idx] = acc;
}

// ---------------------------------------------------------------------------
// Instance-norm: split partials (pass 1), then norm+prelu computing mu/rsig
// inline from the partials (no separate finalize kernel).
// ---------------------------------------------------------------------------
__global__ void inorm_part(const float* __restrict__ in, float* __restrict__ part,
                           int vox) {
    const int blk = blockIdx.x;      // 0..7
    const int nc = blockIdx.y;
    const int seg4 = vox >> 5;
    const float4* p = (const float4*)(in + (size_t)nc * vox) + (size_t)blk * seg4;
    float s = 0.f, s2 = 0.f;
    for (int i = threadIdx.x; i < seg4; i += 256) {
        float4 v = p[i];
        s  += v.x + v.y + v.z + v.w;
        s2 += v.x * v.x + v.y * v.y + v.z * v.z + v.w * v.w;
    }
    __shared__ float sh[256], sh2[256];
    sh[threadIdx.x] = s;
    sh2[threadIdx.x] = s2;
    __syncthreads();
    for (int o = 128; o > 0; o >>= 1) {
        if (threadIdx.x < o) {
            sh[threadIdx.x]  += sh[threadIdx.x + o];
            sh2[threadIdx.x] += sh2[threadIdx.x + o];
        }
        __syncthreads();
    }
    if (threadIdx.x == 0) {
        part[nc * 16 + blk] = sh[0];
        part[nc * 16 + 8 + blk] = sh2[0];
    }
}

// norm+prelu with inline stats finalize from partials. grid (vox/1024, NC).
__global__ void norm_prelu(float* __restrict__ data, const float* __restrict__ part,
                           const float* __restrict__ alpha, int vox) {
    int nc = blockIdx.y;
    __shared__ float s_m, s_rs;
    if (threadIdx.x == 0) {
        float s = 0.f, s2 = 0.f;
        #pragma unroll
        for (int b = 0; b < 8; b++) {
            s  += part[nc * 16 + b];
            s2 += part[nc * 16 + 8 + b];
        }
        float m = s / (float)vox;
        s_m = m;
        s_rs = rsqrtf(s2 / (float)vox - m * m + 1e-5f);
    }
    __syncthreads();
    int i = (blockIdx.x * 256 + threadIdx.x) << 2;
    if (i >= vox) return;
    float m = s_m, rs = s_rs, a = *alpha;
    float4* p = (float4*)(data + (size_t)nc * vox + i);
    float4 v = *p;
    v.x = (v.x - m) * rs; v.x = v.x >= 0.f ? v.x : a * v.x;
    v.y = (v.y - m) * rs; v.y = v.y >= 0.f ? v.y : a * v.y;
    v.z = (v.z - m) * rs; v.z = v.z >= 0.f ? v.z : a * v.z;
    v.w = (v.w - m) * rs; v.w = v.w >= 0.f ? v.w : a * v.w;
    *p = v;
}

__global__ void resize_tri2(const float* __restrict__ in1, float* __restrict__ out1,
                            const float* __restrict__ in2, float* __restrict__ out2,
                            int C, int inD, int outD, float gain) {
    const int ov = outD * outD * outD;
    const int iv = inD * inD * inD;
    int idx = blockIdx.x * blockDim.x + threadIdx.x;
    int total = C * ov;
    if (idx >= total) return;
    const float* in = blockIdx.y ? in2 : in1;
    float* out = blockIdx.y ? out2 : out1;
    int p = idx % ov;
    int c = idx / ov;
    int x = p % outD;
    int t = p / outD;
    int y = t % outD;
    int z = t / outD;

    float r = (float)(inD - 1) / (float)(outD - 1);
    float cz = z * r, cy = y * r, cx = x * r;
    int z0 = min(max((int)floorf(cz), 0), inD - 2);
    int y0 = min(max((int)floorf(cy), 0), inD - 2);
    int x0 = min(max((int)floorf(cx), 0), inD - 2);
    float tz = cz - (float)z0;
    float ty = cy - (float)y0;
    float tx = cx - (float)x0;

    const float* ip = in + (size_t)c * iv;
    size_t b000 = ((size_t)z0 * inD + y0) * inD + x0;
    size_t sy = inD, sz = (size_t)inD * inD;
    float v000 = ip[b000],           v001 = ip[b000 + 1];
    float v010 = ip[b000 + sy],      v011 = ip[b000 + sy + 1];
    float v100 = ip[b000 + sz],      v101 = ip[b000 + sz + 1];
    float v110 = ip[b000 + sz + sy], v111 = ip[b000 + sz + sy + 1];

    float c00 = v000 * (1.f - tx) + v001 * tx;
    float c01 = v010 * (1.f - tx) + v011 * tx;
    float c10 = v100 * (1.f - tx) + v101 * tx;
    float c11 = v110 * (1.f - tx) + v111 * tx;
    float c0 = c00 * (1.f - ty) + c01 * ty;
    float c1 = c10 * (1.f - ty) + c11 * ty;
    out[idx] = gain * (c0 * (1.f - tz) + c1 * tz);
}

__device__ __forceinline__ void calc_taps(float fz, float fy, float fx,
                                          int z, int y, int x, int D,
                                          int* offs, float* wts) {
    float zz = (float)z + fz;
    float yy = (float)y + fy;
    float xx = (float)x + fx;
    float zf = floorf(zz), yf = floorf(yy), xf = floorf(xx);
    int z0 = (int)zf, y0 = (int)yf, x0 = (int)xf;
    float wz = zz - zf, wy = yy - yf, wx = xx - xf;
    int k = 0;
    #pragma unroll
    for (int dz = 0; dz < 2; dz++) {
        int zi = z0 + dz;
        bool vz = (zi >= 0) && (zi < D);
        int zc = min(max(zi, 0), D - 1);
        float gz = dz ? wz : 1.f - wz;
        #pragma unroll
        for (int dy = 0; dy < 2; dy++) {
            int yi = y0 + dy;
            bool vy = (yi >= 0) && (yi < D);
            int yc = min(max(yi, 0), D - 1);
            float gy = dy ? wy : 1.f - wy;
            #pragma unroll
            for (int dx = 0; dx < 2; dx++) {
                int xi = x0 + dx;
                bool vx = (xi >= 0) && (xi < D);
                int xc = min(max(xi, 0), D - 1);
                float gx = dx ? wx : 1.f - wx;
                offs[k] = (zc * D + yc) * D + xc;
                wts[k] = (vz && vy && vx) ? gz * gy * gx : 0.f;
                k++;
            }
        }
    }
}

// vecint squaring step with fused input scale AND optional final composition:
// v := s*in; r = v + sample(v, grid+v); if (up) r += sample(up, grid+r).
__global__ void warp_step(const float* __restrict__ in, float* __restrict__ out,
                          const float* __restrict__ up, float s, int D) {
    const int vox = D * D * D;
    int idx = blockIdx.x * blockDim.x + threadIdx.x;
    if (idx >= vox) return;
    int x = idx % D;
    int t = idx / D;
    int y = t % D;
    int z = t / D;

    float f0 = s * in[idx];
    float f1 = s * in[vox + idx];
    float f2 = s * in[2 * vox + idx];

    int offs[8];
    float wts[8];
    calc_taps(f0, f1, f2, z, y, x, D, offs, wts);

    float a0 = f0, a1 = f1, a2 = f2;
    #pragma unroll
    for (int j = 0; j < 8; j++) {
        float w = s * wts[j];
        a0 += in[offs[j]] * w;
        a1 += in[vox + offs[j]] * w;
        a2 += in[2 * vox + offs[j]] * w;
    }

    if (up) {
        // composition: a += sample(up, grid + a)
        calc_taps(a0, a1, a2, z, y, x, D, offs, wts);
        #pragma unroll
        for (int j = 0; j < 8; j++) {
            float w = wts[j];
            a0 += up[offs[j]] * w;
            a1 += up[vox + offs[j]] * w;
            a2 += up[2 * vox + offs[j]] * w;
        }
    }

    out[idx] = a0;
    out[vox + idx] = a1;
    out[2 * vox + idx] = a2;
}

__global__ void warp_cat(const float* __restrict__ xi, const float* __restrict__ yi,
                         const float* __restrict__ up, float* __restrict__ cat, int D) {
    const int vox = D * D * D;
    int idx = blockIdx.x * blockDim.x + threadIdx.x;
    if (idx >= vox) return;

    int offs[8];
    float wts[8];
    bool w = (up != nullptr);
    if (w) {
        int x = idx % D;
        int t = idx / D;
        int y = t % D;
        int z = t / D;
        calc_taps(up[idx], up[vox + idx], up[2 * vox + idx], z, y, x, D, offs, wts);
    }
    for (int c = 0; c < 16; c++) {
        const float* sp = xi + (size_t)c * vox;
        float xw;
        if (w) {
            xw = 0.f;
            #pragma unroll
            for (int j = 0; j < 8; j++) xw += sp[offs[j]] * wts[j];
        } else {
            xw = sp[idx];
        }
        float b = yi[(size_t)c * vox + idx];
        cat[(size_t)c * vox + idx] = b + xw;
        cat[(size_t)(16 + c) * vox + idx] = b - xw;
    }
}

__global__ void vecint_small(const float* __restrict__ flow, const float* __restrict__ up,
                             float* __restrict__ bufA, float* __restrict__ bufB,
                             int D, float scale, int steps) {
    const int vox = D * D * D;
    const int T = blockDim.x;
    const int tid = threadIdx.x;

    for (int i = tid; i < 3 * vox; i += T) bufA[i] = flow[i] * scale;
    __syncthreads();

    float* cur = bufA;
    float* nxt = bufB;
    for (int s = 0; s < steps; s++) {
        for (int idx = tid; idx < vox; idx += T) {
            int x = idx % D;
            int t = idx / D;
            int y = t % D;
            int z = t / D;
            int offs[8];
            float wts[8];
            calc_taps(cur[idx], cur[vox + idx], cur[2 * vox + idx], z, y, x, D,
                      offs, wts);
            #pragma unroll
            for (int c = 0; c < 3; c++) {
                const float* sp = cur + c * vox;
                float acc = sp[idx];
                #pragma unroll
                for (int j = 0; j < 8; j++) acc += sp[offs[j]] * wts[j];
                nxt[c * vox + idx] = acc;
            }
        }
        __syncthreads();
        float* tmp = cur; cur = nxt; nxt = tmp;
    }

    if (up) {
        for (int idx = tid; idx < vox; idx += T) {
            int x = idx % D;
            int t = idx / D;
            int y = t % D;
            int z = t / D;
            int offs[8];
            float wts[8];
            calc_taps(cur[idx], cur[vox + idx], cur[2 * vox + idx], z, y, x, D,
                      offs, wts);
            #pragma unroll
            for (int c = 0; c < 3; c++) {
                const float* sp = up + c * vox;
                float acc = 0.f;
                #pragma unroll
                for (int j = 0; j < 8; j++) acc += sp[offs[j]] * wts[j];
                cur[c * vox + idx] += acc;
            }
        }
    }
}

// ---------------------------------------------------------------------------
struct Ptrs {
    float *bufA, *bufB, *xs, *ys, *cat, *feat1, *feat2;
    float *vecA, *up, *part, *wrep;
};
static Ptrs P;
static bool g_inited = false;

static void init_ptrs() {
    cudaGetSymbolAddress((void**)&P.bufA, g_bufA);
    cudaGetSymbolAddress((void**)&P.bufB, g_bufB);
    cudaGetSymbolAddress((void**)&P.xs, g_xs);
    cudaGetSymbolAddress((void**)&P.ys, g_ys);
    cudaGetSymbolAddress((void**)&P.cat, g_cat);
    cudaGetSymbolAddress((void**)&P.feat1, g_feat1);
    cudaGetSymbolAddress((void**)&P.feat2, g_feat2);
    cudaGetSymbolAddress((void**)&P.vecA, g_vecA);
    cudaGetSymbolAddress((void**)&P.up, g_up);
    cudaGetSymbolAddress((void**)&P.part, g_part);
    cudaGetSymbolAddress((void**)&P.wrep, g_wrepAll);
}

struct RInfo { int cin, cout, cop, off; };
static const RInfo RI[12] = {
    {1,16,16,0}, {16,32,32,432}, {32,16,16,14256},
    {32,32,32,28080}, {32,27,32,55728}, {27,3,4,83376},
    {32,32,32,86292}, {32,27,32,113940}, {27,3,4,141588},
    {32,32,32,144504}, {32,27,32,172152}, {27,3,4,199800},
};

static void launch_conv_t(int id, const float* in, const float* b, float* outp,
                          int D, int relu, int N) {
    const RInfo& r = RI[id];
    int JCO = (r.cout >= 8) ? 4 : 1;
    int W = 4 * JCO;
    int gy = (r.cout + W - 1) / W;
    int tilesX = (D + 31) / 32;
    int tilesY = D / 4;
    int tilesZ = D / 4;
    dim3 grid(tilesX * tilesY * tilesZ, gy, N);
    const float* wr = P.wrep + r.off;
    if (JCO == 4)
        conv_tiled6<4><<<grid, 128>>>(in, wr, b, outp, r.cin, r.cout, r.cop, D,
                                      relu, tilesX, tilesY);
    else
        conv_tiled6<1><<<grid, 128>>>(in, wr, b, outp, r.cin, r.cout, r.cop, D,
                                      relu, tilesX, tilesY);
}

extern "C" void kernel_launch(void* const* d_in, const int* in_sizes, int n_in,
                              void* d_out, int out_size) {
    (void)in_sizes; (void)n_in; (void)out_size;
    if (!g_inited) { init_ptrs(); g_inited = true; }

    const float* x      = (const float*)d_in[0];
    const float* y      = (const float*)d_in[1];
    const float* enc_w1 = (const float*)d_in[2];
    const float* enc_b1 = (const float*)d_in[3];
    const float* enc_w2 = (const float*)d_in[4];
    const float* enc_b2 = (const float*)d_in[5];
    const float* enc_w3 = (const float*)d_in[6];
    const float* enc_b3 = (const float*)d_in[7];
    const float* prelu1 = (const float*)d_in[8];
    const float* prelu2 = (const float*)d_in[9];
    const float* prelu3 = (const float*)d_in[10];
    const float* dw_w1  = (const float*)d_in[11];
    const float* dw_b1  = (const float*)d_in[12];
    const float* dw_w2  = (const float*)d_in[13];
    const float* dw_b2  = (const float*)d_in[14];
    const float* dw_w3  = (const float*)d_in[15];
    const float* dw_b3  = (const float*)d_in[16];
    float* out = (float*)d_out;

    const int TB = 256;

    repack_all<<<dim3(108, 12), 256>>>(enc_w1, enc_w2, enc_w3,
                                       dw_w1, dw_w2, dw_w3, P.wrep);

    cudaMemcpyAsync(P.bufA, x, (size_t)V64 * 4, cudaMemcpyDeviceToDevice);
    cudaMemcpyAsync(P.bufA + V64, y, (size_t)V64 * 4, cudaMemcpyDeviceToDevice);

    launch_conv_t(0, P.bufA, enc_b1, P.bufB, 64, 0, 2);
    inorm_part<<<dim3(8, 32), 256>>>(P.bufB, P.part, V64);
    norm_prelu<<<dim3(V64 / 1024, 32), 256>>>(P.bufB, P.part, prelu1, V64);
    launch_conv_t(1, P.bufB, enc_b2, P.bufA, 64, 0, 2);
    inorm_part<<<dim3(8, 64), 256>>>(P.bufA, P.part, V64);
    norm_prelu<<<dim3(V64 / 1024, 64), 256>>>(P.bufA, P.part, prelu2, V64);
    launch_conv_t(2, P.bufA, enc_b3, P.bufB, 64, 0, 2);
    inorm_part<<<dim3(8, 32), 256>>>(P.bufB, P.part, V64);
    norm_prelu<<<dim3(V64 / 1024, 32), 256>>>(P.bufB, P.part, prelu3, V64);

    static const int OFF[5] = {0, 262144, 294912, 299008, 299520};
    const float* xs_lv[5];
    const float* ys_lv[5];
    xs_lv[0] = P.bufB;
    ys_lv[0] = P.bufB + (size_t)16 * V64;
    for (int i = 1; i < 5; i++) {
        xs_lv[i] = P.xs + (size_t)16 * OFF[i];
        ys_lv[i] = P.ys + (size_t)16 * OFF[i];
    }
    for (int i = 1; i < 5; i++) {
        int inD = 64 >> (i - 1), outD = 64 >> i;
        int total = 16 * outD * outD * outD;
        resize_tri2<<<dim3((total + TB - 1) / TB, 2), TB>>>(
            xs_lv[i - 1], (float*)xs_lv[i], ys_lv[i - 1], (float*)ys_lv[i],
            16, inD, outD, 1.f);
    }

    static const size_t int_off[5] = {0, 786432, 884736, 897024, 898560};
    const size_t pos_base = 898752;

    for (int L = 4; L >= 0; L--) {
        int s = 64 >> L;
        int vox = s * s * s;
        int sb = (vox + TB - 1) / TB;
        const float* up = (L < 4) ? P.up : nullptr;
        float* flowL = out + int_off[L];
        float* posL  = out + pos_base + int_off[L];

        warp_cat<<<sb, TB>>>(xs_lv[L], ys_lv[L], up, P.cat, s);

        if (s >= 16) {
            launch_conv_t(3 + L * 3 + 0, P.cat,   dw_b1 + (size_t)L * 32, P.feat1, s, 1, 1);
            launch_conv_t(3 + L * 3 + 1, P.feat1, dw_b2 + (size_t)L * 27, P.feat2, s, 1, 1);
            launch_conv_t(3 + L * 3 + 2, P.feat2, dw_b3 + (size_t)L * 3,  flowL,   s, 0, 1);
        } else {
            conv3x3x3<<<dim3(sb, 32, 1), TB, 32 * 27 * 4>>>(
                P.cat, dw_w1 + (size_t)L * 32 * 32 * 27, dw_b1 + (size_t)L * 32,
                P.feat1, 32, s, 1);
            conv3x3x3<<<dim3(sb, 27, 1), TB, 32 * 27 * 4>>>(
                P.feat1, dw_w2 + (size_t)L * 27 * 32 * 27, dw_b2 + (size_t)L * 27,
                P.feat2, 32, s, 1);
            conv3x3x3<<<dim3(sb, 3, 1), TB, 27 * 27 * 4>>>(
                P.feat2, dw_w3 + (size_t)L * 3 * 27 * 27, dw_b3 + (size_t)L * 3,
                flowL, 27, s, 0);
        }

        if (s <= 16) {
            vecint_small<<<1, 1024>>>(flowL, up, P.vecA, posL, s, 1.f / 128.f, 7);
        } else {
            // 7 squaring steps; last one fuses the optional composition.
            const float* cur = flowL;
            for (int step = 0; step < 7; step++) {
                float* dst = (step & 1) ? P.vecA : posL;
                float sc = (step == 0) ? (1.f / 128.f) : 1.f;
                const float* upArg = (step == 6) ? up : nullptr;
                warp_step<<<sb, TB>>>(cur, dst, upArg, sc, s);
                cur = dst;
            }
            // step 6 (7th) wrote posL with composition fused
        }

        if (L > 0) {
            int outD = 2 * s;
            int total = 3 * outD * outD * outD;
            resize_tri2<<<dim3((total + TB - 1) / TB, 1), TB>>>(
                posL, P.up, posL, P.up, 3, s, outD, 2.f);
        }
    }
}

// round 13
// speedup vs baseline: 1.0187x; 1.0187x over previous
#include <cuda_runtime.h>

// ---------------------------------------------------------------------------
// encoderOnlyComplex: VoxelMorph-style registration network, fp32.
// Round 13: R12 base; vecint for D=16 moved from single-block vecint_small
// to the grid-parallel warp_step path (16 blocks vs 1 SM). All else
// unchanged from the measured 2458 µs kernel.
// ---------------------------------------------------------------------------

#define V64 262144            // 64^3
#define PYR_TOT 299584

__device__ float g_bufA[2 * 32 * V64];
__device__ float g_bufB[2 * 32 * V64];
__device__ float g_xs[16 * PYR_TOT];
__device__ float g_ys[16 * PYR_TOT];
__device__ float g_cat[32 * V64];
__device__ float g_feat1[32 * V64];
__device__ float g_feat2[27 * V64];
__device__ float g_vecA[3 * V64];
__device__ float g_up[3 * V64];
__device__ float g_part[64 * 16];     // per-(nc) partials: [nc][0..7]=s, [nc][8..15]=s2
__device__ float g_wrepAll[202716];

// ---- cp.async helpers ----
__device__ __forceinline__ void cp_async4(void* smem, const void* gmem, bool pred) {
    unsigned s = (unsigned)__cvta_generic_to_shared(smem);
    int sz = pred ? 4 : 0;
    asm volatile("cp.async.ca.shared.global [%0], [%1], 4, %2;"
                 :: "r"(s), "l"(gmem), "r"(sz));
}
#define CP_COMMIT() asm volatile("cp.async.commit_group;")
#define CP_WAIT1()  asm volatile("cp.async.wait_group 1;")
#define CP_WAIT0()  asm volatile("cp.async.wait_group 0;")

__global__ void repack_all(const float* __restrict__ e1, const float* __restrict__ e2,
                           const float* __restrict__ e3, const float* __restrict__ w1,
                           const float* __restrict__ w2, const float* __restrict__ w3,
                           float* __restrict__ wr) {
    const int CIN[12]  = {1,16,32, 32,32,27, 32,32,27, 32,32,27};
    const int COUT[12] = {16,32,16, 32,27,3, 32,27,3, 32,27,3};
    const int COP[12]  = {16,32,16, 32,32,4, 32,32,4, 32,32,4};
    const int OFF[12]  = {0,432,14256, 28080,55728,83376,
                          86292,113940,141588, 144504,172152,199800};
    int id = blockIdx.y;
    int cin = CIN[id], cout = COUT[id], cop = COP[id];
    int tot = cin * 27 * cop;
    int i = blockIdx.x * blockDim.x + threadIdx.x;
    if (i >= tot) return;
    const float* src;
    if (id == 0) src = e1;
    else if (id == 1) src = e2;
    else if (id == 2) src = e3;
    else {
        int l = (id - 3) / 3, j = (id - 3) % 3;
        const float* base = (j == 0) ? w1 : (j == 1) ? w2 : w3;
        src = base + (size_t)l * cout * cin * 27;
    }
    int co = i % cop;
    int k  = (i / cop) % 27;
    int ci = i / (cop * 27);
    wr[OFF[id] + i] = (co < cout) ? src[((size_t)co * cin + ci) * 27 + k] : 0.f;
}

// ---------------------------------------------------------------------------
// Conv v6 (measured best): 128 thr, JCO co-groups via blockIdx.y, tile
// 32x4x4, double-buffered cp.async staging. UNCHANGED.
// ---------------------------------------------------------------------------
template <int JCO>
__global__ __launch_bounds__(128)
void conv_tiled6(const float* __restrict__ in, const float* __restrict__ wr,
                 const float* __restrict__ bias, float* __restrict__ out,
                 int Cin, int Cout, int COP, int D, int relu,
                 int tilesX, int tilesY) {
    const int W = 4 * JCO;
    __shared__ __align__(16) float s_in[2][6 * 6 * 36];
    __shared__ __align__(16) float s_w[2][27 * 16];

    const int tid = threadIdx.x;
    const int tx = tid & 7;
    const int ty = (tid >> 3) & 3;
    const int tg = tid >> 5;

    int bx = blockIdx.x;
    const int tX = bx % tilesX;
    bx /= tilesX;
    const int tY = bx % tilesY;
    const int tZ = bx / tilesY;
    const int n  = blockIdx.z;

    const int X0 = tX * 32;
    const int Y0 = tY * 4;
    const int Z0 = tZ * 4;
    const int coB = blockIdx.y * W;
    const int x0 = X0 + (tx << 2);
    const int yo = Y0 + ty;
    const int vox = D * D * D;

    float acc[4 * JCO * 4];
    #pragma unroll
    for (int j = 0; j < JCO; j++) {
        int co = coB + tg * JCO + j;
        float b = (co < Cout) ? bias[co] : 0.f;
        #pragma unroll
        for (int zo = 0; zo < 4; zo++)
            #pragma unroll
            for (int xo = 0; xo < 4; xo++) acc[(zo * JCO + j) * 4 + xo] = b;
    }

    const float* inN = in + (size_t)n * Cin * vox;

    auto stage = [&](int ci, int buf) {
        for (int i = tid; i < 27 * W; i += 128)
            cp_async4(&s_w[buf][(i / W) * W + (i % W)],
                      &wr[((size_t)ci * 27 + i / W) * COP + coB + (i % W)], true);
        const float* inC = inN + (size_t)ci * vox;
        for (int i = tid; i < 1224; i += 128) {
            int p = i / 204;
            int r = (i % 204) / 34;
            int c = i % 34;
            int zz = Z0 - 1 + p;
            int yy = Y0 - 1 + r;
            int xx = X0 - 1 + c;
            bool ok = (unsigned)zz < (unsigned)D && (unsigned)yy < (unsigned)D &&
                      (unsigned)xx < (unsigned)D;
            int zc = min(max(zz, 0), D - 1);
            int yc = min(max(yy, 0), D - 1);
            int xc = min(max(xx, 0), D - 1);
            cp_async4(&s_in[buf][(p * 6 + r) * 36 + c],
                      &inC[((size_t)zc * D + yc) * D + xc], ok);
        }
        CP_COMMIT();
    };

    stage(0, 0);
    for (int ci = 0; ci < Cin; ci++) {
        if (ci + 1 < Cin) {
            stage(ci + 1, (ci + 1) & 1);
            CP_WAIT1();
        } else {
            CP_WAIT0();
        }
        __syncthreads();

        const int buf = ci & 1;
        #pragma unroll
        for (int kz = 0; kz < 3; kz++) {
            #pragma unroll
            for (int ky = 0; ky < 3; ky++) {
                const int k0 = kz * 9 + ky * 3;
                float wk[3][JCO];
                if (JCO == 4) {
                    #pragma unroll
                    for (int kx = 0; kx < 3; kx++) {
                        float4 w4 = *(const float4*)&s_w[buf][(k0 + kx) * 16 + tg * 4];
                        wk[kx][0] = w4.x; wk[kx][1] = w4.y;
                        wk[kx][2] = w4.z; wk[kx][3] = w4.w;
                    }
                } else {
                    #pragma unroll
                    for (int kx = 0; kx < 3; kx++)
                        wk[kx][0] = s_w[buf][(k0 + kx) * W + tg];
                }
                #pragma unroll
                for (int zo = 0; zo < 4; zo++) {
                    const float* bp =
                        &s_in[buf][((kz + zo) * 6 + ty + ky) * 36 + (tx << 2)];
                    float4 a = *(const float4*)bp;
                    float4 b = *(const float4*)(bp + 4);
                    float v[6] = {a.x, a.y, a.z, a.w, b.x, b.y};
                    #pragma unroll
                    for (int kx = 0; kx < 3; kx++)
                        #pragma unroll
                        for (int j = 0; j < JCO; j++)
                            #pragma unroll
                            for (int xo = 0; xo < 4; xo++)
                                acc[(zo * JCO + j) * 4 + xo] +=
                                    v[kx + xo] * wk[kx][j];
                }
            }
        }
        __syncthreads();
    }

    if (x0 < D) {
        #pragma unroll
        for (int zo = 0; zo < 4; zo++) {
            int z = Z0 + zo;
            #pragma unroll
            for (int j = 0; j < JCO; j++) {
                int co = coB + tg * JCO + j;
                if (co < Cout) {
                    float4 r;
                    float* a = &acc[(zo * JCO + j) * 4];
                    r.x = a[0]; r.y = a[1]; r.z = a[2]; r.w = a[3];
                    if (relu) {
                        r.x = fmaxf(r.x, 0.f); r.y = fmaxf(r.y, 0.f);
                        r.z = fmaxf(r.z, 0.f); r.w = fmaxf(r.w, 0.f);
                    }
                    *(float4*)(out + ((size_t)n * Cout + co) * vox +
                               ((size_t)z * D + yo) * D + x0) = r;
                }
            }
        }
    }
}

// Fallback direct conv for tiny volumes (D < 16).
__global__ void conv3x3x3(const float* __restrict__ in, const float* __restrict__ w,
                          const float* __restrict__ bias, float* __restrict__ out,
                          int Cin, int D, int do_relu) {
    const int vox = D * D * D;
    const int co = blockIdx.y;
    const int n  = blockIdx.z;
    extern __shared__ float ws[];
    const int nw = Cin * 27;
    for (int i = threadIdx.x; i < nw; i += blockDim.x)
        ws[i] = w[(size_t)co * nw + i];
    __syncthreads();

    int idx = blockIdx.x * blockDim.x + threadIdx.x;
    if (idx >= vox) return;
    int x = idx % D;
    int t = idx / D;
    int y = t % D;
    int z = t / D;

    const float* inb = in + (size_t)n * Cin * vox;
    float acc = bias[co];
    for (int ci = 0; ci < Cin; ci++) {
        const float* ip = inb + (size_t)ci * vox;
        const float* wp = ws + ci * 27;
        #pragma unroll
        for (int kz = 0; kz < 3; kz++) {
            int zz = z + kz - 1;
            if ((unsigned)zz >= (unsigned)D) continue;
            #pragma unroll
            for (int ky = 0; ky < 3; ky++) {
                int yy = y + ky - 1;
                if ((unsigned)yy >= (unsigned)D) continue;
                const float* row = ip + ((size_t)zz * D + yy) * D;
                #pragma unroll
                for (int kx = 0; kx < 3; kx++) {
                    int xx = x + kx - 1;
                    if ((unsigned)xx >= (unsigned)D) continue;
                    acc += row[xx] * wp[kz * 9 + ky * 3 + kx];
                }
            }
        }
    }
    if (do_relu) acc = fmaxf(acc, 0.f);
    out[((size_t)n * gridDim.y + co) * vox + idx] = acc;
}

// ---------------------------------------------------------------------------
// Instance-norm: split partials, then norm+prelu with inline finalize.
// ---------------------------------------------------------------------------
__global__ void inorm_part(const float* __restrict__ in, float* __restrict__ part,
                           int vox) {
    const int blk = blockIdx.x;      // 0..7
    const int nc = blockIdx.y;
    const int seg4 = vox >> 5;
    const float4* p = (const float4*)(in + (size_t)nc * vox) + (size_t)blk * seg4;
    float s = 0.f, s2 = 0.f;
    for (int i = threadIdx.x; i < seg4; i += 256) {
        float4 v = p[i];
        s  += v.x + v.y + v.z + v.w;
        s2 += v.x * v.x + v.y * v.y + v.z * v.z + v.w * v.w;
    }
    __shared__ float sh[256], sh2[256];
    sh[threadIdx.x] = s;
    sh2[threadIdx.x] = s2;
    __syncthreads();
    for (int o = 128; o > 0; o >>= 1) {
        if (threadIdx.x < o) {
            sh[threadIdx.x]  += sh[threadIdx.x + o];
            sh2[threadIdx.x] += sh2[threadIdx.x + o];
        }
        __syncthreads();
    }
    if (threadIdx.x == 0) {
        part[nc * 16 + blk] = sh[0];
        part[nc * 16 + 8 + blk] = sh2[0];
    }
}

__global__ void norm_prelu(float* __restrict__ data, const float* __restrict__ part,
                           const float* __restrict__ alpha, int vox) {
    int nc = blockIdx.y;
    __shared__ float s_m, s_rs;
    if (threadIdx.x == 0) {
        float s = 0.f, s2 = 0.f;
        #pragma unroll
        for (int b = 0; b < 8; b++) {
            s  += part[nc * 16 + b];
            s2 += part[nc * 16 + 8 + b];
        }
        float m = s / (float)vox;
        s_m = m;
        s_rs = rsqrtf(s2 / (float)vox - m * m + 1e-5f);
    }
    __syncthreads();
    int i = (blockIdx.x * 256 + threadIdx.x) << 2;
    if (i >= vox) return;
    float m = s_m, rs = s_rs, a = *alpha;
    float4* p = (float4*)(data + (size_t)nc * vox + i);
    float4 v = *p;
    v.x = (v.x - m) * rs; v.x = v.x >= 0.f ? v.x : a * v.x;
    v.y = (v.y - m) * rs; v.y = v.y >= 0.f ? v.y : a * v.y;
    v.z = (v.z - m) * rs; v.z = v.z >= 0.f ? v.z : a * v.z;
    v.w = (v.w - m) * rs; v.w = v.w >= 0.f ? v.w : a * v.w;
    *p = v;
}

__global__ void resize_tri2(const float* __restrict__ in1, float* __restrict__ out1,
                            const float* __restrict__ in2, float* __restrict__ out2,
                            int C, int inD, int outD, float gain) {
    const int ov = outD * outD * outD;
    const int iv = inD * inD * inD;
    int idx = blockIdx.x * blockDim.x + threadIdx.x;
    int total = C * ov;
    if (idx >= total) return;
    const float* in = blockIdx.y ? in2 : in1;
    float* out = blockIdx.y ? out2 : out1;
    int p = idx % ov;
    int c = idx / ov;
    int x = p % outD;
    int t = p / outD;
    int y = t % outD;
    int z = t / outD;

    float r = (float)(inD - 1) / (float)(outD - 1);
    float cz = z * r, cy = y * r, cx = x * r;
    int z0 = min(max((int)floorf(cz), 0), inD - 2);
    int y0 = min(max((int)floorf(cy), 0), inD - 2);
    int x0 = min(max((int)floorf(cx), 0), inD - 2);
    float tz = cz - (float)z0;
    float ty = cy - (float)y0;
    float tx = cx - (float)x0;

    const float* ip = in + (size_t)c * iv;
    size_t b000 = ((size_t)z0 * inD + y0) * inD + x0;
    size_t sy = inD, sz = (size_t)inD * inD;
    float v000 = ip[b000],           v001 = ip[b000 + 1];
    float v010 = ip[b000 + sy],      v011 = ip[b000 + sy + 1];
    float v100 = ip[b000 + sz],      v101 = ip[b000 + sz + 1];
    float v110 = ip[b000 + sz + sy], v111 = ip[b000 + sz + sy + 1];

    float c00 = v000 * (1.f - tx) + v001 * tx;
    float c01 = v010 * (1.f - tx) + v011 * tx;
    float c10 = v100 * (1.f - tx) + v101 * tx;
    float c11 = v110 * (1.f - tx) + v111 * tx;
    float c0 = c00 * (1.f - ty) + c01 * ty;
    float c1 = c10 * (1.f - ty) + c11 * ty;
    out[idx] = gain * (c0 * (1.f - tz) + c1 * tz);
}

__device__ __forceinline__ void calc_taps(float fz, float fy, float fx,
                                          int z, int y, int x, int D,
                                          int* offs, float* wts) {
    float zz = (float)z + fz;
    float yy = (float)y + fy;
    float xx = (float)x + fx;
    float zf = floorf(zz), yf = floorf(yy), xf = floorf(xx);
    int z0 = (int)zf, y0 = (int)yf, x0 = (int)xf;
    float wz = zz - zf, wy = yy - yf, wx = xx - xf;
    int k = 0;
    #pragma unroll
    for (int dz = 0; dz < 2; dz++) {
        int zi = z0 + dz;
        bool vz = (zi >= 0) && (zi < D);
        int zc = min(max(zi, 0), D - 1);
        float gz = dz ? wz : 1.f - wz;
        #pragma unroll
        for (int dy = 0; dy < 2; dy++) {
            int yi = y0 + dy;
            bool vy = (yi >= 0) && (yi < D);
            int yc = min(max(yi, 0), D - 1);
            float gy = dy ? wy : 1.f - wy;
            #pragma unroll
            for (int dx = 0; dx < 2; dx++) {
                int xi = x0 + dx;
                bool vx = (xi >= 0) && (xi < D);
                int xc = min(max(xi, 0), D - 1);
                float gx = dx ? wx : 1.f - wx;
                offs[k] = (zc * D + yc) * D + xc;
                wts[k] = (vz && vy && vx) ? gz * gy * gx : 0.f;
                k++;
            }
        }
    }
}

// vecint squaring step with fused input scale AND optional final composition.
__global__ void warp_step(const float* __restrict__ in, float* __restrict__ out,
                          const float* __restrict__ up, float s, int D) {
    const int vox = D * D * D;
    int idx = blockIdx.x * blockDim.x + threadIdx.x;
    if (idx >= vox) return;
    int x = idx % D;
    int t = idx / D;
    int y = t % D;
    int z = t / D;

    float f0 = s * in[idx];
    float f1 = s * in[vox + idx];
    float f2 = s * in[2 * vox + idx];

    int offs[8];
    float wts[8];
    calc_taps(f0, f1, f2, z, y, x, D, offs, wts);

    float a0 = f0, a1 = f1, a2 = f2;
    #pragma unroll
    for (int j = 0; j < 8; j++) {
        float w = s * wts[j];
        a0 += in[offs[j]] * w;
        a1 += in[vox + offs[j]] * w;
        a2 += in[2 * vox + offs[j]] * w;
    }

    if (up) {
        calc_taps(a0, a1, a2, z, y, x, D, offs, wts);
        #pragma unroll
        for (int j = 0; j < 8; j++) {
            float w = wts[j];
            a0 += up[offs[j]] * w;
            a1 += up[vox + offs[j]] * w;
            a2 += up[2 * vox + offs[j]] * w;
        }
    }

    out[idx] = a0;
    out[vox + idx] = a1;
    out[2 * vox + idx] = a2;
}

__global__ void warp_cat(const float* __restrict__ xi, const float* __restrict__ yi,
                         const float* __restrict__ up, float* __restrict__ cat, int D) {
    const int vox = D * D * D;
    int idx = blockIdx.x * blockDim.x + threadIdx.x;
    if (idx >= vox) return;

    int offs[8];
    float wts[8];
    bool w = (up != nullptr);
    if (w) {
        int x = idx % D;
        int t = idx / D;
        int y = t % D;
        int z = t / D;
        calc_taps(up[idx], up[vox + idx], up[2 * vox + idx], z, y, x, D, offs, wts);
    }
    for (int c = 0; c < 16; c++) {
        const float* sp = xi + (size_t)c * vox;
        float xw;
        if (w) {
            xw = 0.f;
            #pragma unroll
            for (int j = 0; j < 8; j++) xw += sp[offs[j]] * wts[j];
        } else {
            xw = sp[idx];
        }
        float b = yi[(size_t)c * vox + idx];
        cat[(size_t)c * vox + idx] = b + xw;
        cat[(size_t)(16 + c) * vox + idx] = b - xw;
    }
}

__global__ void vecint_small(const float* __restrict__ flow, const float* __restrict__ up,
                             float* __restrict__ bufA, float* __restrict__ bufB,
                             int D, float scale, int steps) {
    const int vox = D * D * D;
    const int T = blockDim.x;
    const int tid = threadIdx.x;

    for (int i = tid; i < 3 * vox; i += T) bufA[i] = flow[i] * scale;
    __syncthreads();

    float* cur = bufA;
    float* nxt = bufB;
    for (int s = 0; s < steps; s++) {
        for (int idx = tid; idx < vox; idx += T) {
            int x = idx % D;
            int t = idx / D;
            int y = t % D;
            int z = t / D;
            int offs[8];
            float wts[8];
            calc_taps(cur[idx], cur[vox + idx], cur[2 * vox + idx], z, y, x, D,
                      offs, wts);
            #pragma unroll
            for (int c = 0; c < 3; c++) {
                const float* sp = cur + c * vox;
                float acc = sp[idx];
                #pragma unroll
                for (int j = 0; j < 8; j++) acc += sp[offs[j]] * wts[j];
                nxt[c * vox + idx] = acc;
            }
        }
        __syncthreads();
        float* tmp = cur; cur = nxt; nxt = tmp;
    }

    if (up) {
        for (int idx = tid; idx < vox; idx += T) {
            int x = idx % D;
            int t = idx / D;
            int y = t % D;
            int z = t / D;
            int offs[8];
            float wts[8];
            calc_taps(cur[idx], cur[vox + idx], cur[2 * vox + idx], z, y, x, D,
                      offs, wts);
            #pragma unroll
            for (int c = 0; c < 3; c++) {
                const float* sp = up + c * vox;
                float acc = 0.f;
                #pragma unroll
                for (int j = 0; j < 8; j++) acc += sp[offs[j]] * wts[j];
                cur[c * vox + idx] += acc;
            }
        }
    }
}

// ---------------------------------------------------------------------------
struct Ptrs {
    float *bufA, *bufB, *xs, *ys, *cat, *feat1, *feat2;
    float *vecA, *up, *part, *wrep;
};
static Ptrs P;
static bool g_inited = false;

static void init_ptrs() {
    cudaGetSymbolAddress((void**)&P.bufA, g_bufA);
    cudaGetSymbolAddress((void**)&P.bufB, g_bufB);
    cudaGetSymbolAddress((void**)&P.xs, g_xs);
    cudaGetSymbolAddress((void**)&P.ys, g_ys);
    cudaGetSymbolAddress((void**)&P.cat, g_cat);
    cudaGetSymbolAddress((void**)&P.feat1, g_feat1);
    cudaGetSymbolAddress((void**)&P.feat2, g_feat2);
    cudaGetSymbolAddress((void**)&P.vecA, g_vecA);
    cudaGetSymbolAddress((void**)&P.up, g_up);
    cudaGetSymbolAddress((void**)&P.part, g_part);
    cudaGetSymbolAddress((void**)&P.wrep, g_wrepAll);
}

struct RInfo { int cin, cout, cop, off; };
static const RInfo RI[12] = {
    {1,16,16,0}, {16,32,32,432}, {32,16,16,14256},
    {32,32,32,28080}, {32,27,32,55728}, {27,3,4,83376},
    {32,32,32,86292}, {32,27,32,113940}, {27,3,4,141588},
    {32,32,32,144504}, {32,27,32,172152}, {27,3,4,199800},
};

static void launch_conv_t(int id, const float* in, const float* b, float* outp,
                          int D, int relu, int N) {
    const RInfo& r = RI[id];
    int JCO = (r.cout >= 8) ? 4 : 1;
    int W = 4 * JCO;
    int gy = (r.cout + W - 1) / W;
    int tilesX = (D + 31) / 32;
    int tilesY = D / 4;
    int tilesZ = D / 4;
    dim3 grid(tilesX * tilesY * tilesZ, gy, N);
    const float* wr = P.wrep + r.off;
    if (JCO == 4)
        conv_tiled6<4><<<grid, 128>>>(in, wr, b, outp, r.cin, r.cout, r.cop, D,
                                      relu, tilesX, tilesY);
    else
        conv_tiled6<1><<<grid, 128>>>(in, wr, b, outp, r.cin, r.cout, r.cop, D,
                                      relu, tilesX, tilesY);
}

extern "C" void kernel_launch(void* const* d_in, const int* in_sizes, int n_in,
                              void* d_out, int out_size) {
    (void)in_sizes; (void)n_in; (void)out_size;
    if (!g_inited) { init_ptrs(); g_inited = true; }

    const float* x      = (const float*)d_in[0];
    const float* y      = (const float*)d_in[1];
    const float* enc_w1 = (const float*)d_in[2];
    const float* enc_b1 = (const float*)d_in[3];
    const float* enc_w2 = (const float*)d_in[4];
    const float* enc_b2 = (const float*)d_in[5];
    const float* enc_w3 = (const float*)d_in[6];
    const float* enc_b3 = (const float*)d_in[7];
    const float* prelu1 = (const float*)d_in[8];
    const float* prelu2 = (const float*)d_in[9];
    const float* prelu3 = (const float*)d_in[10];
    const float* dw_w1  = (const float*)d_in[11];
    const float* dw_b1  = (const float*)d_in[12];
    const float* dw_w2  = (const float*)d_in[13];
    const float* dw_b2  = (const float*)d_in[14];
    const float* dw_w3  = (const float*)d_in[15];
    const float* dw_b3  = (const float*)d_in[16];
    float* out = (float*)d_out;

    const int TB = 256;

    repack_all<<<dim3(108, 12), 256>>>(enc_w1, enc_w2, enc_w3,
                                       dw_w1, dw_w2, dw_w3, P.wrep);

    cudaMemcpyAsync(P.bufA, x, (size_t)V64 * 4, cudaMemcpyDeviceToDevice);
    cudaMemcpyAsync(P.bufA + V64, y, (size_t)V64 * 4, cudaMemcpyDeviceToDevice);

    launch_conv_t(0, P.bufA, enc_b1, P.bufB, 64, 0, 2);
    inorm_part<<<dim3(8, 32), 256>>>(P.bufB, P.part, V64);
    norm_prelu<<<dim3(V64 / 1024, 32), 256>>>(P.bufB, P.part, prelu1, V64);
    launch_conv_t(1, P.bufB, enc_b2, P.bufA, 64, 0, 2);
    inorm_part<<<dim3(8, 64), 256>>>(P.bufA, P.part, V64);
    norm_prelu<<<dim3(V64 / 1024, 64), 256>>>(P.bufA, P.part, prelu2, V64);
    launch_conv_t(2, P.bufA, enc_b3, P.bufB, 64, 0, 2);
    inorm_part<<<dim3(8, 32), 256>>>(P.bufB, P.part, V64);
    norm_prelu<<<dim3(V64 / 1024, 32), 256>>>(P.bufB, P.part, prelu3, V64);

    static const int OFF[5] = {0, 262144, 294912, 299008, 299520};
    const float* xs_lv[5];
    const float* ys_lv[5];
    xs_lv[0] = P.bufB;
    ys_lv[0] = P.bufB + (size_t)16 * V64;
    for (int i = 1; i < 5; i++) {
        xs_lv[i] = P.xs + (size_t)16 * OFF[i];
        ys_lv[i] = P.ys + (size_t)16 * OFF[i];
    }
    for (int i = 1; i < 5; i++) {
        int inD = 64 >> (i - 1), outD = 64 >> i;
        int total = 16 * outD * outD * outD;
        resize_tri2<<<dim3((total + TB - 1) / TB, 2), TB>>>(
            xs_lv[i - 1], (float*)xs_lv[i], ys_lv[i - 1], (float*)ys_lv[i],
            16, inD, outD, 1.f);
    }

    static const size_t int_off[5] = {0, 786432, 884736, 897024, 898560};
    const size_t pos_base = 898752;

    for (int L = 4; L >= 0; L--) {
        int s = 64 >> L;
        int vox = s * s * s;
        int sb = (vox + TB - 1) / TB;
        const float* up = (L < 4) ? P.up : nullptr;
        float* flowL = out + int_off[L];
        float* posL  = out + pos_base + int_off[L];

        warp_cat<<<sb, TB>>>(xs_lv[L], ys_lv[L], up, P.cat, s);

        if (s >= 16) {
            launch_conv_t(3 + L * 3 + 0, P.cat,   dw_b1 + (size_t)L * 32, P.feat1, s, 1, 1);
            launch_conv_t(3 + L * 3 + 1, P.feat1, dw_b2 + (size_t)L * 27, P.feat2, s, 1, 1);
            launch_conv_t(3 + L * 3 + 2, P.feat2, dw_b3 + (size_t)L * 3,  flowL,   s, 0, 1);
        } else {
            conv3x3x3<<<dim3(sb, 32, 1), TB, 32 * 27 * 4>>>(
                P.cat, dw_w1 + (size_t)L * 32 * 32 * 27, dw_b1 + (size_t)L * 32,
                P.feat1, 32, s, 1);
            conv3x3x3<<<dim3(sb, 27, 1), TB, 32 * 27 * 4>>>(
                P.feat1, dw_w2 + (size_t)L * 27 * 32 * 27, dw_b2 + (size_t)L * 27,
                P.feat2, 32, s, 1);
            conv3x3x3<<<dim3(sb, 3, 1), TB, 27 * 27 * 4>>>(
                P.feat2, dw_w3 + (size_t)L * 3 * 27 * 27, dw_b3 + (size_t)L * 3,
                flowL, 27, s, 0);
        }

        if (s <= 8) {
            // tiny levels: fused single-block vecint (+compose); 7 steps -> posL
            vecint_small<<<1, 1024>>>(flowL, up, P.vecA, posL, s, 1.f / 128.f, 7);
        } else {
            // D >= 16: grid-parallel squaring steps; final step fuses compose.
            const float* cur = flowL;
            for (int step = 0; step < 7; step++) {
                float* dst = (step & 1) ? P.vecA : posL;
                float sc = (step == 0) ? (1.f / 128.f) : 1.f;
                const float* upArg = (step == 6) ? up : nullptr;
                warp_step<<<sb, TB>>>(cur, dst, upArg, sc, s);
                cur = dst;
            }
        }

        if (L > 0) {
            int outD = 2 * s;
            int total = 3 * outD * outD * outD;
            resize_tri2<<<dim3((total + TB - 1) / TB, 1), TB>>>(
                posL, P.up, posL, P.up, 3, s, outD, 2.f);
        }
    }
}